// round 14
// baseline (speedup 1.0000x reference)
#include <cuda_runtime.h>
#include <cstdint>

#define KST   48
#define TLEN  512
#define TILE  4               // steps per tile (= renorm cadence)
#define BDIM  32              // one warp; 4 batches (2 pairs x 2 half-warps)
#define ETS   208             // per-batch tile float stride (192 + pad)

// ---- packed f32x2 helpers (sm_100+) ----
__device__ __forceinline__ unsigned long long fma2(unsigned long long a,
                                                   unsigned long long b,
                                                   unsigned long long c) {
    unsigned long long d;
    asm("fma.rn.f32x2 %0, %1, %2, %3;" : "=l"(d) : "l"(a), "l"(b), "l"(c));
    return d;
}
__device__ __forceinline__ unsigned long long add2(unsigned long long a,
                                                   unsigned long long b) {
    unsigned long long d;
    asm("add.rn.f32x2 %0, %1, %2;" : "=l"(d) : "l"(a), "l"(b));
    return d;
}
__device__ __forceinline__ unsigned long long pack2(float lo, float hi) {
    unsigned long long r;
    asm("mov.b64 %0, {%1, %2};" : "=l"(r) : "f"(lo), "f"(hi));
    return r;
}
__device__ __forceinline__ float2 unpack2(unsigned long long v) {
    float2 f;
    asm("mov.b64 {%0, %1}, %2;" : "=f"(f.x), "=f"(f.y) : "l"(v));
    return f;
}
__device__ __forceinline__ float ex2f(float x) {
    float y; asm("ex2.approx.f32 %0, %1;" : "=f"(y) : "f"(x)); return y;
}
__device__ __forceinline__ float lg2f(float x) {
    float y; asm("lg2.approx.f32 %0, %1;" : "=f"(y) : "f"(x)); return y;
}

#define LOG2E 1.4426950408889634f
#define LN2   0.6931471805599453f

__global__ __launch_bounds__(BDIM)
void crf_nll_kernel(const float* __restrict__ emis,   // [B, T, K]
                    const int*   __restrict__ lab,    // [B, T]
                    const float* __restrict__ trans,  // [K, K]
                    float*       __restrict__ out)    // [B]
{
    __shared__ __align__(16) float etile[4][ETS];        // EXP'd weights, 4 batches
    __shared__ __align__(16) float pbuf[2][2][2][KST];   // [parity][pair][half][state]

    const int tid = threadIdx.x;
    const int h   = tid >> 4;          // half-warp
    const int l   = tid & 15;          // lane within half
    const int b0  = blockIdx.x * 4 + h;        // pair X batch
    const int b1  = blockIdx.x * 4 + 2 + h;    // pair Y batch

    const float* ebx = emis + (size_t)b0 * TLEN * KST;
    const float* eby = emis + (size_t)b1 * TLEN * KST;
    const int*   lbx = lab  + b0 * TLEN;
    const int*   lby = lab  + b1 * TLEN;

    // E columns for states l, l+16, l+32 (SHARED by both pairs): 24 f32x2 each
    unsigned long long ecA[KST / 2], ecB[KST / 2], ecC[KST / 2];
#pragma unroll
    for (int q = 0; q < KST / 2; ++q) {
        const float* t0 = trans + (2 * q) * KST;
        const float* t1 = trans + (2 * q + 1) * KST;
        ecA[q] = pack2(__expf(t0[l]),      __expf(t1[l]));
        ecB[q] = pack2(__expf(t0[l + 16]), __expf(t1[l + 16]));
        ecC[q] = pack2(__expf(t0[l + 32]), __expf(t1[l + 32]));
    }

    // ---- sequence scores (unary + binary), 16 lanes per batch ----
    float sx = 0.f, sy = 0.f;
    for (int t = l; t < TLEN; t += 16) {
        int lx = lbx[t];
        sx += ebx[t * KST + lx];
        if (t + 1 < TLEN) sx += trans[lx * KST + lbx[t + 1]];
        int ly = lby[t];
        sy += eby[t * KST + ly];
        if (t + 1 < TLEN) sy += trans[ly * KST + lby[t + 1]];
    }
#pragma unroll
    for (int d = 8; d >= 1; d >>= 1) {
        sx += __shfl_xor_sync(0xffffffffu, sx, d, 16);
        sy += __shfl_xor_sync(0xffffffffu, sy, d, 16);
    }

    // ---- forward recursion, LINEAR domain, exact pow2 renorm ----
    float x0 = ex2f(ebx[l] * LOG2E), x1 = ex2f(ebx[l + 16] * LOG2E), x2 = ex2f(ebx[l + 32] * LOG2E);
    float y0 = ex2f(eby[l] * LOG2E), y1 = ex2f(eby[l + 16] * LOG2E), y2 = ex2f(eby[l + 32] * LOG2E);
    float Mx = 0.f, My = 0.f;

    const float4* s4x = (const float4*)ebx;
    const float4* s4y = (const float4*)eby;
    const int     maxf4 = (TLEN * KST) / 4 - 1;
    float* tileX = &etile[h][0];          // pair X batches in slots 0,1
    float* tileY = &etile[2 + h][0];      // pair Y batches in slots 2,3

    // prefetch tile 0 (t = 1..4): 48 float4 per batch, 3 per lane
    float4 rx[3], ry[3];
#pragma unroll
    for (int k = 0; k < 3; ++k) {
        rx[k] = s4x[12 + l + 16 * k];
        ry[k] = s4y[12 + l + 16 * k];
    }

    int par = 0;
    for (int gt = 0; gt < 128; ++gt) {    // 127 full tiles + 3-step tail (gt=127)
        // renormalize both pairs: exact pow2 scale
        float mx = fmaxf(x0, fmaxf(x1, x2));
        float my = fmaxf(y0, fmaxf(y1, y2));
#pragma unroll
        for (int d = 8; d >= 1; d >>= 1) {
            mx = fmaxf(mx, __shfl_xor_sync(0xffffffffu, mx, d, 16));
            my = fmaxf(my, __shfl_xor_sync(0xffffffffu, my, d, 16));
        }
        float kx = ceilf(lg2f(mx)), ky = ceilf(lg2f(my));
        float cx = ex2f(-kx),       cy = ex2f(-ky);      // exact pow2 rescale
        x0 *= cx; x1 *= cx; x2 *= cx;  Mx += kx;
        y0 *= cy; y1 *= cy; y2 *= cy;  My += ky;

        // commit current tiles as EXP'd weights
#pragma unroll
        for (int k = 0; k < 3; ++k) {
            float4 v = rx[k];
            v.x = ex2f(v.x * LOG2E); v.y = ex2f(v.y * LOG2E);
            v.z = ex2f(v.z * LOG2E); v.w = ex2f(v.w * LOG2E);
            ((float4*)tileX)[l + 16 * k] = v;
            float4 u = ry[k];
            u.x = ex2f(u.x * LOG2E); u.y = ex2f(u.y * LOG2E);
            u.z = ex2f(u.z * LOG2E); u.w = ex2f(u.w * LOG2E);
            ((float4*)tileY)[l + 16 * k] = u;
        }

        // prefetch next tile (clamped rows land only in unread tail pad)
        if (gt + 1 < 128) {
            int base = (5 + TILE * gt) * (KST / 4);
#pragma unroll
            for (int k = 0; k < 3; ++k) {
                rx[k] = s4x[min(base + l + 16 * k, maxf4)];
                ry[k] = s4y[min(base + l + 16 * k, maxf4)];
            }
        }
        __syncwarp();

#pragma unroll
        for (int tt = 0; tt < TILE; ++tt) {
            const int t = 1 + TILE * gt + tt;
            if (t >= TLEN) break;                 // uniform

            float* pbX = &pbuf[par][0][h][0];
            float* pbY = &pbuf[par][1][h][0];
            pbX[l] = x0; pbX[l + 16] = x1; pbX[l + 32] = x2;
            pbY[l] = y0; pbY[l + 16] = y1; pbY[l + 32] = y2;
            __syncwarp();

            float wx0 = tileX[tt * KST + l];
            float wx1 = tileX[tt * KST + l + 16];
            float wx2 = tileX[tt * KST + l + 32];
            float wy0 = tileY[tt * KST + l];
            float wy1 = tileY[tt * KST + l + 16];
            float wy2 = tileY[tt * KST + l + 32];

            const ulonglong2* ppX = (const ulonglong2*)pbX;
            const ulonglong2* ppY = (const ulonglong2*)pbY;
            unsigned long long xA0 = 0, xA1 = 0, xB0 = 0, xB1 = 0, xC0 = 0, xC1 = 0;
            unsigned long long yA0 = 0, yA1 = 0, yB0 = 0, yB1 = 0, yC0 = 0, yC1 = 0;
#pragma unroll
            for (int q = 0; q < KST / 4; ++q) {   // interleaved dual-pair dot
                ulonglong2 vx = ppX[q];
                ulonglong2 vy = ppY[q];
                xA0 = fma2(vx.x, ecA[2 * q],     xA0);
                yA0 = fma2(vy.x, ecA[2 * q],     yA0);
                xA1 = fma2(vx.y, ecA[2 * q + 1], xA1);
                yA1 = fma2(vy.y, ecA[2 * q + 1], yA1);
                xB0 = fma2(vx.x, ecB[2 * q],     xB0);
                yB0 = fma2(vy.x, ecB[2 * q],     yB0);
                xB1 = fma2(vx.y, ecB[2 * q + 1], xB1);
                yB1 = fma2(vy.y, ecB[2 * q + 1], yB1);
                xC0 = fma2(vx.x, ecC[2 * q],     xC0);
                yC0 = fma2(vy.x, ecC[2 * q],     yC0);
                xC1 = fma2(vx.y, ecC[2 * q + 1], xC1);
                yC1 = fma2(vy.y, ecC[2 * q + 1], yC1);
            }
            float2 fx0 = unpack2(add2(xA0, xA1));
            float2 fx1 = unpack2(add2(xB0, xB1));
            float2 fx2 = unpack2(add2(xC0, xC1));
            float2 fy0 = unpack2(add2(yA0, yA1));
            float2 fy1 = unpack2(add2(yB0, yB1));
            float2 fy2 = unpack2(add2(yC0, yC1));

            x0 = (fx0.x + fx0.y) * wx0;
            x1 = (fx1.x + fx1.y) * wx1;
            x2 = (fx2.x + fx2.y) * wx2;
            y0 = (fy0.x + fy0.y) * wy0;
            y1 = (fy1.x + fy1.y) * wy1;
            y2 = (fy2.x + fy2.y) * wy2;
            par ^= 1;
        }
    }

    // ---- final: log_norm = ln(sum p) + ln2 * M ----
    float ssx = x0 + x1 + x2;
    float ssy = y0 + y1 + y2;
#pragma unroll
    for (int d = 8; d >= 1; d >>= 1) {
        ssx += __shfl_xor_sync(0xffffffffu, ssx, d, 16);
        ssy += __shfl_xor_sync(0xffffffffu, ssy, d, 16);
    }

    if (l == 0) {
        out[b0] = LN2 * (lg2f(ssx) + Mx) - sx;
        out[b1] = LN2 * (lg2f(ssy) + My) - sy;
    }
}

extern "C" void kernel_launch(void* const* d_in, const int* in_sizes, int n_in,
                              void* d_out, int out_size)
{
    const float* emis  = (const float*)d_in[0];   // output (B,T,K) fp32
    const int*   lab   = (const int*)  d_in[1];   // label_input (B,T) int32
    const float* trans = (const float*)d_in[2];   // transition_params (K,K) fp32
    float*       outp  = (float*)d_out;           // (B,) fp32

    const int B = out_size;                       // 1024
    crf_nll_kernel<<<B / 4, BDIM>>>(emis, lab, trans, outp);
}

// round 15
// speedup vs baseline: 1.5699x; 1.5699x over previous
#include <cuda_runtime.h>
#include <cstdint>

#define KST   48
#define TLEN  512
#define GRP   16              // lanes per batch
#define NB    2               // batches per block (one warp)
#define BDIM  32
#define TILE  8               // steps per tile (= renorm cadence)
#define ETS   400             // etile per-batch float stride (bank offset 16)

// ---- packed f32x2 helpers (sm_100+) ----
__device__ __forceinline__ unsigned long long fma2(unsigned long long a,
                                                   unsigned long long b,
                                                   unsigned long long c) {
    unsigned long long d;
    asm("fma.rn.f32x2 %0, %1, %2, %3;" : "=l"(d) : "l"(a), "l"(b), "l"(c));
    return d;
}
__device__ __forceinline__ unsigned long long add2(unsigned long long a,
                                                   unsigned long long b) {
    unsigned long long d;
    asm("add.rn.f32x2 %0, %1, %2;" : "=l"(d) : "l"(a), "l"(b));
    return d;
}
__device__ __forceinline__ unsigned long long pack2(float lo, float hi) {
    unsigned long long r;
    asm("mov.b64 %0, {%1, %2};" : "=l"(r) : "f"(lo), "f"(hi));
    return r;
}
__device__ __forceinline__ float2 unpack2(unsigned long long v) {
    float2 f;
    asm("mov.b64 {%0, %1}, %2;" : "=f"(f.x), "=f"(f.y) : "l"(v));
    return f;
}
__device__ __forceinline__ float ex2f(float x) {
    float y; asm("ex2.approx.f32 %0, %1;" : "=f"(y) : "f"(x)); return y;
}
__device__ __forceinline__ float lg2f(float x) {
    float y; asm("lg2.approx.f32 %0, %1;" : "=f"(y) : "f"(x)); return y;
}

#define LOG2E 1.4426950408889634f
#define LN2   0.6931471805599453f

// one recursion step; caller guarantees the step is in-range.
// Per-step __syncwarp retained: it orders STS->LDS and (measured R12) helps
// the HW/compiler schedule; removing it cost ~14us.
#define STEP(TT)                                                               \
{                                                                              \
    float* pb = par ? pb1 : pb0;                                               \
    pb[l] = p0; pb[l + 16] = p1; pb[l + 32] = p2;                              \
    __syncwarp();                                                              \
    float w0 = myTile[(TT) * KST + l];                                         \
    float w1 = myTile[(TT) * KST + l + 16];                                    \
    float w2 = myTile[(TT) * KST + l + 32];                                    \
    const ulonglong2* pp = (const ulonglong2*)pb;                              \
    unsigned long long cA[4] = {0,0,0,0}, cB[4] = {0,0,0,0}, cC[4] = {0,0,0,0};\
    _Pragma("unroll")                                                          \
    for (int q = 0; q < KST / 4; ++q) {                                        \
        ulonglong2 v = pp[q];                                                  \
        const int h0 = (2 * q)     & 3;                                        \
        const int h1 = (2 * q + 1) & 3;                                        \
        cA[h0] = fma2(v.x, ecA[2 * q],     cA[h0]);                            \
        cA[h1] = fma2(v.y, ecA[2 * q + 1], cA[h1]);                            \
        cB[h0] = fma2(v.x, ecB[2 * q],     cB[h0]);                            \
        cB[h1] = fma2(v.y, ecB[2 * q + 1], cB[h1]);                            \
        cC[h0] = fma2(v.x, ecC[2 * q],     cC[h0]);                            \
        cC[h1] = fma2(v.y, ecC[2 * q + 1], cC[h1]);                            \
    }                                                                          \
    float2 f0 = unpack2(add2(add2(cA[0], cA[1]), add2(cA[2], cA[3])));         \
    float2 f1 = unpack2(add2(add2(cB[0], cB[1]), add2(cB[2], cB[3])));         \
    float2 f2 = unpack2(add2(add2(cC[0], cC[1]), add2(cC[2], cC[3])));         \
    p0 = (f0.x + f0.y) * w0;                                                   \
    p1 = (f1.x + f1.y) * w1;                                                   \
    p2 = (f2.x + f2.y) * w2;                                                   \
    par ^= 1;                                                                  \
}

// exact pow2 renorm via exponent bits (no MUFU on this path)
#define RENORM()                                                               \
{                                                                              \
    float m = fmaxf(p0, fmaxf(p1, p2));                                        \
    _Pragma("unroll")                                                          \
    for (int d = 8; d >= 1; d >>= 1)                                           \
        m = fmaxf(m, __shfl_xor_sync(0xffffffffu, m, d, 16));                  \
    int kk = (int)(__float_as_uint(m) >> 23) - 126;  /* ceil(lg2 m) (+-1 ok) */\
    float sc = __uint_as_float((unsigned)(127 - kk) << 23);  /* 2^-kk exact */ \
    p0 *= sc; p1 *= sc; p2 *= sc;                                              \
    M += (float)kk;                                                            \
}

#define COMMIT()                                                               \
{                                                                              \
    _Pragma("unroll")                                                          \
    for (int k = 0; k < 6; ++k) {                                              \
        float4 v = r[k];                                                       \
        v.x = ex2f(v.x * LOG2E);                                               \
        v.y = ex2f(v.y * LOG2E);                                               \
        v.z = ex2f(v.z * LOG2E);                                               \
        v.w = ex2f(v.w * LOG2E);                                               \
        ((float4*)myTile)[l + 16 * k] = v;                                     \
    }                                                                          \
}

__global__ __launch_bounds__(BDIM)
void crf_nll_kernel(const float* __restrict__ emis,   // [B, T, K]
                    const int*   __restrict__ lab,    // [B, T]
                    const float* __restrict__ trans,  // [K, K]
                    float*       __restrict__ out)    // [B]
{
    __shared__ __align__(16) float etile[NB * ETS];      // EXP'd emission weights
    __shared__ __align__(16) float pbuf[2][NB][KST];     // ping-pong p (linear)

    const int tid = threadIdx.x;
    const int g   = tid >> 4;          // batch within block (0/1)
    const int l   = tid & 15;          // lane within batch group
    const int b   = blockIdx.x * NB + g;

    const float* eb = emis + (size_t)b * TLEN * KST;
    const int*   lb = lab  + b * TLEN;

    // E columns for states l, l+16, l+32 as 24 packed f32x2 each (pairs over i)
    unsigned long long ecA[KST / 2], ecB[KST / 2], ecC[KST / 2];
#pragma unroll
    for (int q = 0; q < KST / 2; ++q) {
        const float* t0 = trans + (2 * q) * KST;
        const float* t1 = trans + (2 * q + 1) * KST;
        ecA[q] = pack2(__expf(t0[l]),      __expf(t1[l]));
        ecB[q] = pack2(__expf(t0[l + 16]), __expf(t1[l + 16]));
        ecC[q] = pack2(__expf(t0[l + 32]), __expf(t1[l + 32]));
    }

    // ---- sequence score (unary + binary), strided over 16 lanes ----
    float part = 0.f;
    for (int t = l; t < TLEN; t += GRP) {
        int l0 = lb[t];
        part += eb[t * KST + l0];
        if (t + 1 < TLEN) part += trans[l0 * KST + lb[t + 1]];
    }
#pragma unroll
    for (int d = 8; d >= 1; d >>= 1)
        part += __shfl_xor_sync(0xffffffffu, part, d, 16);
    const float score = part;

    // ---- forward recursion, LINEAR domain with exact pow2 renorm ----
    float p0 = ex2f(eb[l]      * LOG2E);
    float p1 = ex2f(eb[l + 16] * LOG2E);
    float p2 = ex2f(eb[l + 32] * LOG2E);
    float M  = 0.f;                      // accumulated log2 scale (integer-valued)

    const float4* src4  = (const float4*)eb;
    const int     maxf4 = (TLEN * KST) / 4 - 1;
    float*        myTile = etile + g * ETS;
    float*        pb0 = &pbuf[0][g][0];
    float*        pb1 = &pbuf[1][g][0];

    // prefetch tile 0 (t = 1..8): 96 float4 per batch, 6 per lane
    float4 r[6];
#pragma unroll
    for (int k = 0; k < 6; ++k)
        r[k] = src4[12 + l + 16 * k];

    int par = 0;
    for (int gt = 0; gt < 63; ++gt) {            // 63 full tiles (t = 1..504)
        RENORM();
        COMMIT();
        {   // prefetch tile gt+1 (clamped rows land only in unread tail pad)
            int base = (9 + TILE * gt) * (KST / 4);
#pragma unroll
            for (int k = 0; k < 6; ++k)
                r[k] = src4[min(base + l + 16 * k, maxf4)];
        }
        __syncwarp();

#pragma unroll
        for (int tt = 0; tt < TILE; ++tt) {      // no bounds check: always valid
            STEP(tt);
        }
    }

    // ---- tail tile: t = 505..511 (7 steps) ----
    RENORM();
    COMMIT();
    __syncwarp();
#pragma unroll
    for (int tt = 0; tt < 7; ++tt) {
        STEP(tt);
    }

    // ---- final: log_norm = ln(sum p) + ln2 * M ----
    float ssum = p0 + p1 + p2;
#pragma unroll
    for (int d = 8; d >= 1; d >>= 1)
        ssum += __shfl_xor_sync(0xffffffffu, ssum, d, 16);

    if (l == 0)
        out[b] = LN2 * (lg2f(ssum) + M) - score;
}

extern "C" void kernel_launch(void* const* d_in, const int* in_sizes, int n_in,
                              void* d_out, int out_size)
{
    const float* emis  = (const float*)d_in[0];   // output (B,T,K) fp32
    const int*   lab   = (const int*)  d_in[1];   // label_input (B,T) int32
    const float* trans = (const float*)d_in[2];   // transition_params (K,K) fp32
    float*       outp  = (float*)d_out;           // (B,) fp32

    const int B = out_size;                       // 1024
    crf_nll_kernel<<<B / NB, BDIM>>>(emis, lab, trans, outp);
}

// round 16
// speedup vs baseline: 1.7770x; 1.1319x over previous
#include <cuda_runtime.h>
#include <cstdint>

#define KST   48
#define TLEN  512
#define GRP   16              // lanes per batch
#define NB    2               // batches per block (one warp)
#define BDIM  32
#define TILE  8               // steps per tile (= renorm cadence)
#define ETS   400             // etile per-batch float stride (bank offset 16)

// ---- packed f32x2 helpers (sm_100+) ----
__device__ __forceinline__ unsigned long long fma2(unsigned long long a,
                                                   unsigned long long b,
                                                   unsigned long long c) {
    unsigned long long d;
    asm("fma.rn.f32x2 %0, %1, %2, %3;" : "=l"(d) : "l"(a), "l"(b), "l"(c));
    return d;
}
__device__ __forceinline__ unsigned long long add2(unsigned long long a,
                                                   unsigned long long b) {
    unsigned long long d;
    asm("add.rn.f32x2 %0, %1, %2;" : "=l"(d) : "l"(a), "l"(b));
    return d;
}
__device__ __forceinline__ unsigned long long pack2(float lo, float hi) {
    unsigned long long r;
    asm("mov.b64 %0, {%1, %2};" : "=l"(r) : "f"(lo), "f"(hi));
    return r;
}
__device__ __forceinline__ float2 unpack2(unsigned long long v) {
    float2 f;
    asm("mov.b64 {%0, %1}, %2;" : "=f"(f.x), "=f"(f.y) : "l"(v));
    return f;
}
__device__ __forceinline__ float ex2f(float x) {
    float y; asm("ex2.approx.f32 %0, %1;" : "=f"(y) : "f"(x)); return y;
}
__device__ __forceinline__ float lg2f(float x) {
    float y; asm("lg2.approx.f32 %0, %1;" : "=f"(y) : "f"(x)); return y;
}

#define LOG2E 1.4426950408889634f
#define LN2   0.6931471805599453f

__global__ __launch_bounds__(BDIM)
void crf_nll_kernel(const float* __restrict__ emis,   // [B, T, K]
                    const int*   __restrict__ lab,    // [B, T]
                    const float* __restrict__ trans,  // [K, K]
                    float*       __restrict__ out)    // [B]
{
    __shared__ __align__(16) float etile[NB * ETS];      // EXP'd emission weights
    __shared__ __align__(16) float pbuf[2][NB][KST];     // ping-pong p (linear domain)

    const int tid = threadIdx.x;
    const int g   = tid >> 4;          // batch within block (0/1)
    const int l   = tid & 15;          // lane within batch group
    const int b   = blockIdx.x * NB + g;

    const float* eb = emis + (size_t)b * TLEN * KST;
    const int*   lb = lab  + b * TLEN;

    // E columns for states l, l+16, l+32 as 24 packed f32x2 each (pairs over i)
    unsigned long long ecA[KST / 2], ecB[KST / 2], ecC[KST / 2];
#pragma unroll
    for (int q = 0; q < KST / 2; ++q) {
        const float* t0 = trans + (2 * q) * KST;
        const float* t1 = trans + (2 * q + 1) * KST;
        ecA[q] = pack2(__expf(t0[l]),      __expf(t1[l]));
        ecB[q] = pack2(__expf(t0[l + 16]), __expf(t1[l + 16]));
        ecC[q] = pack2(__expf(t0[l + 32]), __expf(t1[l + 32]));
    }

    // ---- sequence score (unary + binary), strided over 16 lanes ----
    float part = 0.f;
    for (int t = l; t < TLEN; t += GRP) {
        int l0 = lb[t];
        part += eb[t * KST + l0];
        if (t + 1 < TLEN) part += trans[l0 * KST + lb[t + 1]];
    }
#pragma unroll
    for (int d = 8; d >= 1; d >>= 1)
        part += __shfl_xor_sync(0xffffffffu, part, d, 16);
    const float score = part;

    // ---- forward recursion, LINEAR domain with exact pow2 renorm ----
    float p0 = ex2f(eb[l]      * LOG2E);
    float p1 = ex2f(eb[l + 16] * LOG2E);
    float p2 = ex2f(eb[l + 32] * LOG2E);
    float M  = 0.f;                      // accumulated log2 scale (integer-valued)

    const float4* src4  = (const float4*)eb;
    const int     maxf4 = (TLEN * KST) / 4 - 1;
    float*        myTile = etile + g * ETS;
    float*        pb0 = &pbuf[0][g][0];
    float*        pb1 = &pbuf[1][g][0];

    // prefetch tile 0 (t = 1..8): 96 float4 per batch, 6 per lane
    float4 r[6];
#pragma unroll
    for (int k = 0; k < 6; ++k)
        r[k] = src4[12 + l + 16 * k];

    int par = 0;
    for (int gt = 0; gt < 64; ++gt) {
        // renormalize: exact power-of-2 scale via exponent bits (no MUFU)
        float m = fmaxf(p0, fmaxf(p1, p2));
#pragma unroll
        for (int d = 8; d >= 1; d >>= 1)
            m = fmaxf(m, __shfl_xor_sync(0xffffffffu, m, d, 16));
        int kk = (int)(__float_as_uint(m) >> 23) - 126;   // >= ceil(lg2 m), exact int
        float sc = __uint_as_float((unsigned)(127 - kk) << 23);   // 2^-kk, exact
        p0 *= sc; p1 *= sc; p2 *= sc;
        M  += (float)kk;

        // commit current tile as EXP'd weights: w = 2^(e * log2e) = exp(e)
#pragma unroll
        for (int k = 0; k < 6; ++k) {
            float4 v = r[k];
            v.x = ex2f(v.x * LOG2E);
            v.y = ex2f(v.y * LOG2E);
            v.z = ex2f(v.z * LOG2E);
            v.w = ex2f(v.w * LOG2E);
            ((float4*)myTile)[l + 16 * k] = v;
        }

        // prefetch next tile (clamped rows only land in unread tail pad)
        if (gt + 1 < 64) {
            int base = (9 + TILE * gt) * (KST / 4);
#pragma unroll
            for (int k = 0; k < 6; ++k)
                r[k] = src4[min(base + l + 16 * k, maxf4)];
        }
        __syncwarp();

#pragma unroll
        for (int tt = 0; tt < TILE; ++tt) {
            const int t = 1 + TILE * gt + tt;
            if (t >= TLEN) break;                 // uniform

            float* pb = par ? pb1 : pb0;
            pb[l] = p0; pb[l + 16] = p1; pb[l + 32] = p2;
            __syncwarp();

            // pre-exponentiated weights: plain LDS, no MUFU on the chain
            float w0 = myTile[tt * KST + l];
            float w1 = myTile[tt * KST + l + 16];
            float w2 = myTile[tt * KST + l + 32];

            // 4 chains of depth 6 per output (short serial fma tail)
            const ulonglong2* pp = (const ulonglong2*)pb;
            unsigned long long cA[4] = {0,0,0,0}, cB[4] = {0,0,0,0}, cC[4] = {0,0,0,0};
#pragma unroll
            for (int q = 0; q < KST / 4; ++q) {   // 12 x LDS.128 broadcast
                ulonglong2 v = pp[q];
                const int h0 = (2 * q)     & 3;
                const int h1 = (2 * q + 1) & 3;
                cA[h0] = fma2(v.x, ecA[2 * q],     cA[h0]);
                cA[h1] = fma2(v.y, ecA[2 * q + 1], cA[h1]);
                cB[h0] = fma2(v.x, ecB[2 * q],     cB[h0]);
                cB[h1] = fma2(v.y, ecB[2 * q + 1], cB[h1]);
                cC[h0] = fma2(v.x, ecC[2 * q],     cC[h0]);
                cC[h1] = fma2(v.y, ecC[2 * q + 1], cC[h1]);
            }
            float2 f0 = unpack2(add2(add2(cA[0], cA[1]), add2(cA[2], cA[3])));
            float2 f1 = unpack2(add2(add2(cB[0], cB[1]), add2(cB[2], cB[3])));
            float2 f2 = unpack2(add2(add2(cC[0], cC[1]), add2(cC[2], cC[3])));

            p0 = (f0.x + f0.y) * w0;              // no log/exp on the chain
            p1 = (f1.x + f1.y) * w1;
            p2 = (f2.x + f2.y) * w2;
            par ^= 1;
        }
    }

    // ---- final: log_norm = ln(sum p) + ln2 * M ----
    float ssum = p0 + p1 + p2;
#pragma unroll
    for (int d = 8; d >= 1; d >>= 1)
        ssum += __shfl_xor_sync(0xffffffffu, ssum, d, 16);

    if (l == 0)
        out[b] = LN2 * (lg2f(ssum) + M) - score;
}

extern "C" void kernel_launch(void* const* d_in, const int* in_sizes, int n_in,
                              void* d_out, int out_size)
{
    const float* emis  = (const float*)d_in[0];   // output (B,T,K) fp32
    const int*   lab   = (const int*)  d_in[1];   // label_input (B,T) int32
    const float* trans = (const float*)d_in[2];   // transition_params (K,K) fp32
    float*       outp  = (float*)d_out;           // (B,) fp32

    const int B = out_size;                       // 1024
    crf_nll_kernel<<<B / NB, BDIM>>>(emis, lab, trans, outp);
}